// round 17
// baseline (speedup 1.0000x reference)
#include <cuda_runtime.h>
#include <cuda_fp16.h>
#include <cstdint>

// ---------------- problem shapes ----------------
constexpr int NBR = 32;
constexpr int CC  = 384;
constexpr int CZ  = 128;
constexpr int NPC = 2;            // (b,n) pairs per CTA
constexpr int ROWS = NPC * NBR;   // 64 = M
constexpr int BN = 4096;
constexpr int THREADS = 256;      // 8 warps: 2m x 4n

// transposed fp16 weights: [d][k]
__device__ __half g_WsT[CC * CC];
__device__ __half g_WzT[CC * CZ];

// ---------------- smem layout (bytes) — 110,848 total -> 2 CTAs/SM ----------------
constexpr int SA = 784;    // A row stride (384 halves + 8 pad)
constexpr int SZ = 272;    // Z row stride (128 halves + 8 pad)
constexpr int SW = 144;    // W row stride (64 halves + 8 pad), conflict-free ldsm
constexpr uint32_t OFF_A  = 0;                         // 64 x 784  = 50176
constexpr uint32_t OFF_Z  = 50176;                     // 64 x 272  = 17408
constexpr uint32_t OFF_W  = 67584;                     // 2 x 18432 = 36864
constexpr uint32_t WBUF   = 18432;                     // 128 rows x 144B
constexpr uint32_t OFF_SI = 104448;                    // 2x384 fp32 = 3072
constexpr uint32_t OFF_SN = 107520;                    // 2x384 fp32 = 3072
constexpr uint32_t OFF_M  = 110592;                    // 64 fp32
constexpr uint32_t SMEM_TOTAL = 110848;

constexpr int NSTAGE = 24;   // per d-tile: 2 Wz(K64) + 6 Ws(K64); 3 d-tiles

// ---------------- asm helpers ----------------
__device__ __forceinline__ uint32_t smem_u32(const void* p) {
    uint32_t a;
    asm("{ .reg .u64 t; cvta.to.shared.u64 t, %1; cvt.u32.u64 %0, t; }" : "=r"(a) : "l"(p));
    return a;
}
__device__ __forceinline__ void ldsm4(uint32_t& r0, uint32_t& r1, uint32_t& r2, uint32_t& r3,
                                      uint32_t addr) {
    asm volatile("ldmatrix.sync.aligned.m8n8.x4.shared.b16 {%0,%1,%2,%3}, [%4];"
                 : "=r"(r0), "=r"(r1), "=r"(r2), "=r"(r3) : "r"(addr));
}
__device__ __forceinline__ void mma16816(float* c, const uint32_t* a, const uint32_t* b) {
    asm volatile("mma.sync.aligned.m16n8k16.row.col.f32.f16.f16.f32 "
                 "{%0,%1,%2,%3}, {%4,%5,%6,%7}, {%8,%9}, {%0,%1,%2,%3};"
                 : "+f"(c[0]), "+f"(c[1]), "+f"(c[2]), "+f"(c[3])
                 : "r"(a[0]), "r"(a[1]), "r"(a[2]), "r"(a[3]), "r"(b[0]), "r"(b[1]));
}
__device__ __forceinline__ void cp16(uint32_t dst, const void* src) {
    asm volatile("cp.async.cg.shared.global [%0], [%1], 16;" :: "r"(dst), "l"(src));
}

// ---------------- weight fp32 -> fp16 transpose ----------------
__global__ void convert_w_t(const float* __restrict__ Ws, const float* __restrict__ Wz) {
    int i = blockIdx.x * blockDim.x + threadIdx.x;
    if (i < CC * CC) {
        int d = i / CC, k = i % CC;
        g_WsT[i] = __float2half_rn(Ws[k * CC + d]);
    }
    if (i < CC * CZ) {
        int d = i / CZ, k = i % CZ;
        g_WzT[i] = __float2half_rn(Wz[k * CC + d]);
    }
}

// ---------------- W staging: stage s = (dt = s/8, sub = s%8) ----------------
// sub 0..1 -> Wz k-chunks, sub 2..7 -> Ws k-chunks; 128 n-rows x 64 k-cols fp16
__device__ __forceinline__ void issue_w_load(int s, uint32_t dstBase, int tid) {
    const int sub = s & 7, d0 = (s >> 3) * 128;
    const __half* src;
    int rstride;
    if (sub < 2) { src = g_WzT + (size_t)d0 * CZ + sub * 64;       rstride = CZ; }
    else         { src = g_WsT + (size_t)d0 * CC + (sub - 2) * 64; rstride = CC; }
    #pragma unroll
    for (int i = 0; i < 4; i++) {
        int idx = tid + i * THREADS;       // 0..1023 : 128 rows x 8 int4
        int r = idx >> 3, c = idx & 7;
        cp16(dstBase + r * SW + c * 16, src + (size_t)r * rstride + c * 8);
    }
    asm volatile("cp.async.commit_group;");
}

// ---------------- one GEMM stage: acc += A(32m x 64k) @ W(32n x 64k)^T ----------------
__device__ __forceinline__ void gemm_stage(uint32_t aLane, int aMfStride, uint32_t wLane,
                                           float (&acc)[2][4][4], bool zero) {
    if (zero) {
        #pragma unroll
        for (int mf = 0; mf < 2; mf++)
            #pragma unroll
            for (int nf = 0; nf < 4; nf++)
                #pragma unroll
                for (int e = 0; e < 4; e++) acc[mf][nf][e] = 0.f;
    }
    #pragma unroll
    for (int k = 0; k < 4; k++) {
        uint32_t a[2][4];
        #pragma unroll
        for (int mf = 0; mf < 2; mf++)
            ldsm4(a[mf][0], a[mf][1], a[mf][2], a[mf][3], aLane + mf * aMfStride + k * 32);
        uint32_t b[4][2];
        #pragma unroll
        for (int fp = 0; fp < 2; fp++) {
            uint32_t r0, r1, r2, r3;
            ldsm4(r0, r1, r2, r3, wLane + fp * (16 * SW) + k * 32);
            b[2 * fp][0] = r0; b[2 * fp][1] = r1;
            b[2 * fp + 1][0] = r2; b[2 * fp + 1][1] = r3;
        }
        #pragma unroll
        for (int mf = 0; mf < 2; mf++)
            #pragma unroll
            for (int nf = 0; nf < 4; nf++)
                mma16816(acc[mf][nf], a[mf], b[nf]);
    }
}

// ---------------- fused main kernel (2 CTAs/SM, fully independent) ----------------
__global__ void __launch_bounds__(THREADS, 2) fused_kernel(
    const float* __restrict__ s_i,
    const float* __restrict__ s_ij,
    const float* __restrict__ m_ij,
    const float* __restrict__ z_ij,
    const float* __restrict__ gamma,
    const float* __restrict__ beta,
    float* __restrict__ out)
{
    extern __shared__ char smem[];
    const uint32_t sb = smem_u32(smem);
    const int tid = threadIdx.x, warp = tid >> 5, lane = tid & 31;
    const int wm = warp & 1, wn = warp >> 1;      // 2m x 4n warp grid, tile 32m x 32n
    const int bn0 = blockIdx.x * NPC;

    // ---- prefetch W stages 0 and 1
    issue_w_load(0, sb + OFF_W, tid);
    issue_w_load(1, sb + OFF_W + WBUF, tid);

    // ---- load & convert Z = z_ij (64 x 128)
    {
        const float4* g = (const float4*)(z_ij + (size_t)bn0 * NBR * CZ);
        #pragma unroll
        for (int i = 0; i < 4; i++) {
            int idx = tid + i * THREADS;       // 64 rows x 16 col-groups
            int r = idx >> 4, c = idx & 15;
            float4 v0 = g[r * 32 + c * 2];
            float4 v1 = g[r * 32 + c * 2 + 1];
            __half2 h0 = __floats2half2_rn(v0.x, v0.y), h1 = __floats2half2_rn(v0.z, v0.w);
            __half2 h2 = __floats2half2_rn(v1.x, v1.y), h3 = __floats2half2_rn(v1.z, v1.w);
            uint4 u;
            u.x = *(uint32_t*)&h0; u.y = *(uint32_t*)&h1;
            u.z = *(uint32_t*)&h2; u.w = *(uint32_t*)&h3;
            *(uint4*)(smem + OFF_Z + r * SZ + c * 16) = u;
        }
    }
    // ---- s_i (2x384), mask (64)
    {
        const float4* g = (const float4*)(s_i + (size_t)bn0 * CC);
        float4* d = (float4*)(smem + OFF_SI);
        for (int idx = tid; idx < NPC * CC / 4; idx += THREADS) d[idx] = g[idx];
        if (tid < ROWS) ((float*)(smem + OFF_M))[tid] = m_ij[(size_t)bn0 * NBR + tid];
    }
    asm volatile("cp.async.wait_group 0;" ::: "memory");   // W0, W1 resident
    __syncthreads();                                       // Z / si / mask visible

    // ---- lane-resolved base addresses
    const uint32_t aA = sb + OFF_A + (32 * wm + (lane & 15)) * SA + (lane >> 4) * 16;
    const uint32_t aZ = sb + OFF_Z + (32 * wm + (lane & 15)) * SZ + (lane >> 4) * 16;
    const int g8 = lane >> 3;
    const uint32_t wOfs = (uint32_t)((32 * wn + (g8 >> 1) * 8 + (lane & 7)) * SW + (g8 & 1) * 16);

    float cG[2][4][4], cP[2][4][4];

    const float* M_s  = (const float*)(smem + OFF_M);
    const float* SI_s = (const float*)(smem + OFF_SI);
    float*       SN_s = (float*)(smem + OFF_SN);
    const float mv00 = M_s[32 * wm + (lane >> 2)];
    const float mv01 = M_s[32 * wm + (lane >> 2) + 8];
    const float mv10 = M_s[32 * wm + 16 + (lane >> 2)];
    const float mv11 = M_s[32 * wm + 16 + (lane >> 2) + 8];

    // ==== phase B: per-warp A-convert slice (rows [8w,8w+8)), then stage 0 GEMM —
    //      no barrier between, A-load latency hides under other warps' MMA issue.
    {
        const float4* g = (const float4*)(s_ij + (size_t)bn0 * NBR * CC);
        #pragma unroll
        for (int j = 0; j < 12; j++) {
            int idx = warp * 384 + j * 32 + lane;
            int r = idx / 48, gcol = idx % 48;
            float4 v0 = g[r * 96 + gcol * 2];
            float4 v1 = g[r * 96 + gcol * 2 + 1];
            __half2 h0 = __floats2half2_rn(v0.x, v0.y), h1 = __floats2half2_rn(v0.z, v0.w);
            __half2 h2 = __floats2half2_rn(v1.x, v1.y), h3 = __floats2half2_rn(v1.z, v1.w);
            uint4 u;
            u.x = *(uint32_t*)&h0; u.y = *(uint32_t*)&h1;
            u.z = *(uint32_t*)&h2; u.w = *(uint32_t*)&h3;
            *(uint4*)(smem + OFF_A + r * SA + gcol * 16) = u;
        }
        gemm_stage(aZ, 16 * SZ, sb + OFF_W + wOfs, cG, true);   // stage 0 (Wz k0, dt=0)
    }
    __syncthreads();                       // A complete; W buf0 free
    issue_w_load(2, sb + OFF_W, tid);      // stage 2 -> buf0

    // ==== stages 1..23: sub 0-1 Wz chunks -> cG, sub 2-7 Ws chunks -> cP
    for (int s = 1; s < NSTAGE; ++s) {
        const int sub = s & 7, dt = s >> 3;
        const uint32_t wbuf = sb + OFF_W + (uint32_t)(s & 1) * WBUF + wOfs;

        if (sub < 2) gemm_stage(aZ + sub * 128, 16 * SZ, wbuf, cG, sub == 0);
        else         gemm_stage(aA + (sub - 2) * 128, 16 * SA, wbuf, cP, sub == 2);

        if (sub == 7) {
            // epilogue: msg = m*(P - s_i)*G, reduce over this warp's 32 neighbor rows
            const int d0 = dt * 128;
            #pragma unroll
            for (int nf = 0; nf < 4; nf++) {
                const int col0 = d0 + 32 * wn + nf * 8 + (lane & 3) * 2;
                const float si0 = SI_s[wm * CC + col0];
                const float si1 = SI_s[wm * CC + col0 + 1];
                float t0 = mv00 * (cP[0][nf][0] - si0) * cG[0][nf][0]
                         + mv01 * (cP[0][nf][2] - si0) * cG[0][nf][2]
                         + mv10 * (cP[1][nf][0] - si0) * cG[1][nf][0]
                         + mv11 * (cP[1][nf][2] - si0) * cG[1][nf][2];
                float t1 = mv00 * (cP[0][nf][1] - si1) * cG[0][nf][1]
                         + mv01 * (cP[0][nf][3] - si1) * cG[0][nf][3]
                         + mv10 * (cP[1][nf][1] - si1) * cG[1][nf][1]
                         + mv11 * (cP[1][nf][3] - si1) * cG[1][nf][3];
                #pragma unroll
                for (int o = 4; o <= 16; o <<= 1) {
                    t0 += __shfl_xor_sync(0xffffffffu, t0, o);
                    t1 += __shfl_xor_sync(0xffffffffu, t1, o);
                }
                if ((lane >> 2) == 0) {
                    SN_s[wm * CC + col0]     = t0;
                    SN_s[wm * CC + col0 + 1] = t1;
                }
            }
        }
        __syncthreads();                              // CTA done with buf(s&1)
        if (s + 2 < NSTAGE) issue_w_load(s + 2, sb + OFF_W + (uint32_t)(s & 1) * WBUF, tid);
        if (s + 1 < NSTAGE) {
            if (s + 2 < NSTAGE) asm volatile("cp.async.wait_group 1;" ::: "memory");
            else                asm volatile("cp.async.wait_group 0;" ::: "memory");
            __syncthreads();                          // stage s+1 visible
        }
    }

    // ---- fused layernorm: warp w (w<2) handles (b,n) pair w
    __syncthreads();
    if (warp < NPC) {
        const float* x = SN_s + warp * CC;
        float v[12], sm = 0.f, sq = 0.f;
        #pragma unroll
        for (int j = 0; j < 12; j++) {
            v[j] = x[lane + j * 32];
            sm += v[j]; sq += v[j] * v[j];
        }
        #pragma unroll
        for (int o = 16; o; o >>= 1) {
            sm += __shfl_xor_sync(0xffffffffu, sm, o);
            sq += __shfl_xor_sync(0xffffffffu, sq, o);
        }
        const float mu = sm * (1.0f / CC);
        const float var = sq * (1.0f / CC) - mu * mu;
        const float rstd = rsqrtf(var + 1e-6f);
        float* o_ = out + (size_t)(bn0 + warp) * CC;
        #pragma unroll
        for (int j = 0; j < 12; j++) {
            int e = lane + j * 32;
            o_[e] = (v[j] - mu) * rstd * gamma[e] + beta[e];
        }
    }
}

// ---------------- launch ----------------
extern "C" void kernel_launch(void* const* d_in, const int* in_sizes, int n_in,
                              void* d_out, int out_size)
{
    const float* s_i   = (const float*)d_in[0];
    const float* s_ij  = (const float*)d_in[1];
    const float* m_ij  = (const float*)d_in[2];
    const float* z_ij  = (const float*)d_in[3];
    const float* W_s   = (const float*)d_in[4];
    const float* W_z   = (const float*)d_in[5];
    const float* gamma = (const float*)d_in[6];
    const float* beta  = (const float*)d_in[7];
    float* out = (float*)d_out;

    cudaFuncSetAttribute(fused_kernel, cudaFuncAttributeMaxDynamicSharedMemorySize,
                         (int)SMEM_TOTAL);

    convert_w_t<<<(CC * CC + 255) / 256, 256>>>(W_s, W_z);
    fused_kernel<<<BN / NPC, THREADS, SMEM_TOTAL>>>(s_i, s_ij, m_ij, z_ij, gamma, beta, out);
}